// round 17
// baseline (speedup 1.0000x reference)
#include <cuda_runtime.h>

// Scratch via __device__ globals (no allocations allowed).
__device__ float    g_part[8192];
__device__ unsigned g_count = 0;   // self-resetting ticket -> deterministic per call

// MUFU sqrt: single instruction, max rel err ~2^-23, sqrt(0)=0.
__device__ __forceinline__ float fsqrt_approx(float x) {
    float r;
    asm("sqrt.approx.f32 %0, %1;" : "=f"(r) : "f"(x));
    return r;
}

// Blackwell 256-bit global load (LDG.E.256): 8 floats, 32B-aligned.
__device__ __forceinline__ void ldg256(const float* __restrict__ p, float r[8]) {
    asm("ld.global.nc.v8.f32 {%0,%1,%2,%3,%4,%5,%6,%7}, [%8];"
        : "=f"(r[0]), "=f"(r[1]), "=f"(r[2]), "=f"(r[3]),
          "=f"(r[4]), "=f"(r[5]), "=f"(r[6]), "=f"(r[7])
        : "l"(p));
}

// Shapes fixed: [8,3,16,256,256] fp32 -> 384 planes of 256x256 (row = 256 floats).
// FULL-ROW WARPS with 256-BIT LOADS + ROLLING WINDOW (R10 geometry):
//  - lane l owns floats [8l, 8l+8) of the row: ONE LDG.256 per row per thread
//    (vs two LDG.128) -> half the load instructions / L1 wavefronts.
//  - 7 of 8 x-neighbors are register-local; the 8th is lane l+1's element 0:
//    ONE shuffle per row, and its lane31->lane0 wrap IS the circular row wrap.
//  - rolling 1-row-ahead window, 8-row strips, 1536 blocks, 32-reg pin.
// TV magnitude: sqrt((x[h,w]-x[h,w+1])^2 + (x[h,w]-x[h+1,w])^2), circular.
__global__ void __launch_bounds__(256, 8) tv_fused_kernel(const float* __restrict__ in,
                                                          float* __restrict__ out,
                                                          double inv_n) {
    const unsigned FULL = 0xFFFFFFFFu;
    const int lane = threadIdx.x & 31;
    const int wid  = threadIdx.x >> 5;
    const int gw   = blockIdx.x * 8 + wid;    // global warp id
    const int plane = gw >> 5;                // 32 strips per 256x256 plane
    const int h0    = (gw & 31) << 3;         // first row of this warp's 8-row strip
    const int nidx  = (lane + 1) & 31;        // shuffle source (circular)

    const float* __restrict__ pf = in + ((long)plane << 16) + (lane << 3);

    // Current row (h0)
    float rc[8];
    ldg256(pf + (h0 << 8), rc);

    float acc = 0.0f;
    #pragma unroll
    for (int i = 0; i < 8; i++) {
        // Issue next-row load FIRST (independent of current compute).
        float rn[8];
        const int hn = (h0 + i + 1) & 255;    // wraps only for last strip
        ldg256(pf + (hn << 8), rn);

        // Single shuffle: next lane's element 0 (lane31 wraps to lane0 = row wrap).
        const float nx = __shfl_sync(FULL, rc[0], nidx);

        #pragma unroll
        for (int j = 0; j < 8; j++) {
            const float right = (j < 7) ? rc[j + 1] : nx;
            const float dx = rc[j] - right;
            const float dy = rc[j] - rn[j];
            acc += fsqrt_approx(fmaf(dx, dx, dy * dy));
        }

        #pragma unroll
        for (int j = 0; j < 8; j++) rc[j] = rn[j];
    }

    // Warp reduce (8 warps per block)
    #pragma unroll
    for (int o = 16; o > 0; o >>= 1)
        acc += __shfl_xor_sync(FULL, acc, o);

    __shared__ float warpsum[8];
    __shared__ bool  s_last;
    if (lane == 0) warpsum[wid] = acc;
    if (threadIdx.x == 0) s_last = false;
    __syncthreads();

    if (threadIdx.x == 0) {
        float bsum = warpsum[0] + warpsum[1] + warpsum[2] + warpsum[3]
                   + warpsum[4] + warpsum[5] + warpsum[6] + warpsum[7];
        g_part[blockIdx.x] = bsum;
        __threadfence();
        unsigned ticket = atomicAdd(&g_count, 1u);
        if (ticket == gridDim.x - 1) s_last = true;
    }
    __syncthreads();

    // Last block to arrive reduces all partials and writes the output.
    if (s_last) {
        double dsum = 0.0;
        for (int i = threadIdx.x; i < (int)gridDim.x; i += 256)
            dsum += (double)g_part[i];
        #pragma unroll
        for (int o = 16; o > 0; o >>= 1)
            dsum += __shfl_xor_sync(FULL, dsum, o);
        __shared__ double dws[8];
        if (lane == 0) dws[wid] = dsum;
        __syncthreads();
        if (threadIdx.x == 0) {
            double ssum = dws[0] + dws[1] + dws[2] + dws[3]
                        + dws[4] + dws[5] + dws[6] + dws[7];
            out[0] = (float)(ssum * inv_n);
            g_count = 0;   // reset for next (graph-replayed) call
        }
    }
}

extern "C" void kernel_launch(void* const* d_in, const int* in_sizes, int n_in,
                              void* d_out, int out_size) {
    const float* in = (const float*)d_in[0];
    float* out = (float*)d_out;
    const long long n = in_sizes[0];              // 25,165,824
    // 384 planes * 32 strips/plane = 12288 warps = 1536 blocks of 8 warps
    const int threads = 256;
    const int blocks  = (int)(n / (threads * 64));  // 64 elems per thread -> 1536

    tv_fused_kernel<<<blocks, threads>>>(in, out, 1.0 / (double)n);
}